// round 11
// baseline (speedup 1.0000x reference)
#include <cuda_runtime.h>
#include <cuda_fp16.h>
#include <cstdint>

// ============================================================================
// IterativeFixedPoint: z_{k+1} = tanh(W z_k + b + x), z0 = 0, 25 iterations.
// B=32768, F=256. Rows independent -> fused kernel, each CTA owns 64 rows and
// iterates locally. Tensor path: ldmatrix + mma.sync.m16n8k16 (f16 in, f32
// accum) -- the only tensor instructions legal on the plain sm_103 PTX target
// this harness compiles for (tcgen05 needs sm_103a and is rejected by ptxas).
// ============================================================================

#define FEAT       256
#define MTILE      64
#define NBLOCKS    512          // 32768 / 64
#define NTHREADS   256          // 8 warps: 2 row-groups x 4 col-groups
#define MMA_ITERS  24           // iter 1 = tanh(c); + 24 GEMM iters = 25

#define ZS_BYTES   (MTILE * 512)    // 64 rows x 256 f16 = 32 KB (x2 buffers)
#define WS_BYTES   (256 * 512)      // 256 rows x 256 f16 = 128 KB
#define DYNSMEM    (128 + 2 * ZS_BYTES + WS_BYTES)   // 128 align slack

// ---------------------------------------------------------------------------
// helpers
// ---------------------------------------------------------------------------
static __device__ __forceinline__ uint32_t smem_u32(const void* p) {
    uint32_t a;
    asm("{ .reg .u64 t; cvta.to.shared.u64 t, %1; cvt.u32.u64 %0, t; }"
        : "=r"(a) : "l"(p));
    return a;
}

// row-major K storage, 512B per row (256 f16). 16B chunks XOR-swizzled by
// (row & 7) so ldmatrix phases (8 rows, same k-chunk) are conflict-free.
static __device__ __forceinline__ uint32_t swz(uint32_t base, int row, int kchunk) {
    return base + (uint32_t)row * 512u + ((uint32_t)(kchunk ^ (row & 7)) << 4);
}

#define LDSM_X4(r0, r1, r2, r3, addr) \
    asm volatile("ldmatrix.sync.aligned.m8n8.x4.shared.b16 {%0,%1,%2,%3}, [%4];" \
                 : "=r"(r0), "=r"(r1), "=r"(r2), "=r"(r3) : "r"(addr))

#define MMA16816(d, a, b) \
    asm volatile("mma.sync.aligned.m16n8k16.row.col.f32.f16.f16.f32 " \
                 "{%0,%1,%2,%3}, {%4,%5,%6,%7}, {%8,%9}, {%0,%1,%2,%3};" \
                 : "+f"((d)[0]), "+f"((d)[1]), "+f"((d)[2]), "+f"((d)[3]) \
                 : "r"((a)[0]), "r"((a)[1]), "r"((a)[2]), "r"((a)[3]), \
                   "r"((b)[0]), "r"((b)[1]))

// accurate tanh: 1 - 2/(exp2(2u*log2e)+1); ~1e-6 rel err, exact +-1 saturation
static __device__ __forceinline__ float tanh_fast(float u) {
    float e;
    asm("ex2.approx.f32 %0, %1;" : "=f"(e) : "f"(u * 2.885390081777927f));
    float r;
    asm("rcp.approx.f32 %0, %1;" : "=f"(r) : "f"(e + 1.0f));
    return fmaf(-2.0f, r, 1.0f);
}

static __device__ __forceinline__ uint32_t f2h2(float a, float b) {
    __half2 h = __floats2half2_rn(a, b);   // .x = a = low half = even column
    return *reinterpret_cast<uint32_t*>(&h);
}

// ---------------------------------------------------------------------------
// kernel
// ---------------------------------------------------------------------------
__global__ void __launch_bounds__(NTHREADS, 1)
IterativeFixedPoint_kernel(const float* __restrict__ gx,
                           const float* __restrict__ gW,
                           const float* __restrict__ gb,
                           float* __restrict__ gout)
{
    extern __shared__ char smraw[];
    const uint32_t base = (smem_u32(smraw) + 127u) & ~127u;
    const uint32_t zs0 = base;                  // z ping  (64x256 f16)
    const uint32_t zs1 = base + ZS_BYTES;       // z pong
    const uint32_t ws  = base + 2 * ZS_BYTES;   // W       (256x256 f16)

    const int tid  = threadIdx.x;
    const int lane = tid & 31;
    const int warp = tid >> 5;
    const int R0   = (warp & 1) * 32;           // warp row base   (0/32)
    const int C0   = (warp >> 1) * 64;          // warp col base   (0/64/128/192)
    const int rowq = lane >> 2;                 // 0..7
    const int colq = (lane & 3) * 2;            // 0,2,4,6
    const int gRow0 = blockIdx.x * MTILE;

    // ---- W -> smem f16 (thread t owns W row t; swizzled 16B chunks)
    {
        const float4* wr = reinterpret_cast<const float4*>(gW + (size_t)tid * FEAT);
#pragma unroll
        for (int q = 0; q < 32; q++) {          // chunk q = f16 cols [8q, 8q+8)
            float4 a  = wr[2 * q];
            float4 a2 = wr[2 * q + 1];
            uint32_t v0 = f2h2(a.x,  a.y);
            uint32_t v1 = f2h2(a.z,  a.w);
            uint32_t v2 = f2h2(a2.x, a2.y);
            uint32_t v3 = f2h2(a2.z, a2.w);
            asm volatile("st.shared.v4.b32 [%0], {%1,%2,%3,%4};"
                         :: "r"(swz(ws, tid, q)), "r"(v0), "r"(v1), "r"(v2), "r"(v3)
                         : "memory");
        }
    }

    // ---- c = x + b in D-fragment layout: c[mt][nb][j]
    //      j=0,1: row rowq,   cols colq,colq+1 ; j=2,3: row rowq+8
    float c[2][8][4];
    {
        float2 bp[8];
#pragma unroll
        for (int nb = 0; nb < 8; nb++)
            bp[nb] = *reinterpret_cast<const float2*>(gb + C0 + nb * 8 + colq);
#pragma unroll
        for (int mt = 0; mt < 2; mt++)
#pragma unroll
            for (int hh = 0; hh < 2; hh++) {
                int row = R0 + mt * 16 + hh * 8 + rowq;
                const float2* xr = reinterpret_cast<const float2*>(
                    gx + (size_t)(gRow0 + row) * FEAT);
#pragma unroll
                for (int nb = 0; nb < 8; nb++) {
                    float2 xv = xr[(C0 + nb * 8 + colq) >> 1];
                    c[mt][nb][2 * hh + 0] = xv.x + bp[nb].x;
                    c[mt][nb][2 * hh + 1] = xv.y + bp[nb].y;
                }
            }
    }

    // ---- iteration 1: z1 = tanh(c) -> zs0
#pragma unroll
    for (int mt = 0; mt < 2; mt++)
#pragma unroll
        for (int hh = 0; hh < 2; hh++) {
            int row = R0 + mt * 16 + hh * 8 + rowq;
            int bc  = (C0 + colq) * 2;          // byte col of first pair
#pragma unroll
            for (int nb = 0; nb < 8; nb++) {
                uint32_t v = f2h2(tanh_fast(c[mt][nb][2 * hh]),
                                  tanh_fast(c[mt][nb][2 * hh + 1]));
                int bcol = bc + nb * 16;
                uint32_t addr = swz(zs0, row, bcol >> 4) + (bcol & 15);
                asm volatile("st.shared.b32 [%0], %1;" :: "r"(addr), "r"(v) : "memory");
            }
        }
    __syncthreads();

    // ---- iterations 2..25
    const int gA = (lane >> 3);                 // ldmatrix lane group 0..3
    const int arow = ((gA & 1) * 8) + (lane & 7);   // A: row offset within 16
    const int akc  = (gA >> 1);                     // A: k-chunk offset (0/1)
    const int brow = ((gA >> 1) * 8) + (lane & 7);  // B: n offset within 16
    const int bkc  = (gA & 1);                      // B: k-chunk offset (0/1)

#pragma unroll 1
    for (int it = 0; it < MMA_ITERS; it++) {
        const uint32_t rz = (it & 1) ? zs1 : zs0;   // read buffer
        const uint32_t wz = (it & 1) ? zs0 : zs1;   // write buffer

        float d[2][8][4];
#pragma unroll
        for (int mt = 0; mt < 2; mt++)
#pragma unroll
            for (int nb = 0; nb < 8; nb++)
#pragma unroll
                for (int j = 0; j < 4; j++) d[mt][nb][j] = c[mt][nb][j];

#pragma unroll
        for (int ks = 0; ks < 16; ks++) {
            const int kc0 = ks * 2;
            uint32_t a[2][4];
#pragma unroll
            for (int mt = 0; mt < 2; mt++)
                LDSM_X4(a[mt][0], a[mt][1], a[mt][2], a[mt][3],
                        swz(rz, R0 + mt * 16 + arow, kc0 + akc));
            uint32_t b[8][2];
#pragma unroll
            for (int np = 0; np < 4; np++)
                LDSM_X4(b[2 * np][0], b[2 * np][1], b[2 * np + 1][0], b[2 * np + 1][1],
                        swz(ws, C0 + np * 16 + brow, kc0 + bkc));
#pragma unroll
            for (int mt = 0; mt < 2; mt++)
#pragma unroll
                for (int nb = 0; nb < 8; nb++)
                    MMA16816(d[mt][nb], a[mt], b[nb]);
        }

        const bool last = (it == MMA_ITERS - 1);
        if (!last) {
#pragma unroll
            for (int mt = 0; mt < 2; mt++)
#pragma unroll
                for (int hh = 0; hh < 2; hh++) {
                    int row = R0 + mt * 16 + hh * 8 + rowq;
                    int bc  = (C0 + colq) * 2;
#pragma unroll
                    for (int nb = 0; nb < 8; nb++) {
                        uint32_t v = f2h2(tanh_fast(d[mt][nb][2 * hh]),
                                          tanh_fast(d[mt][nb][2 * hh + 1]));
                        int bcol = bc + nb * 16;
                        uint32_t addr = swz(wz, row, bcol >> 4) + (bcol & 15);
                        asm volatile("st.shared.b32 [%0], %1;"
                                     :: "r"(addr), "r"(v) : "memory");
                    }
                }
            __syncthreads();
        } else {
#pragma unroll
            for (int mt = 0; mt < 2; mt++)
#pragma unroll
                for (int hh = 0; hh < 2; hh++) {
                    int row = gRow0 + R0 + mt * 16 + hh * 8 + rowq;
                    float2* o = reinterpret_cast<float2*>(gout + (size_t)row * FEAT);
#pragma unroll
                    for (int nb = 0; nb < 8; nb++) {
                        float2 v = make_float2(tanh_fast(d[mt][nb][2 * hh]),
                                               tanh_fast(d[mt][nb][2 * hh + 1]));
                        o[(C0 + nb * 8 + colq) >> 1] = v;
                    }
                }
        }
    }
}

// ---------------------------------------------------------------------------
// launch
// ---------------------------------------------------------------------------
extern "C" void kernel_launch(void* const* d_in, const int* in_sizes, int n_in,
                              void* d_out, int out_size)
{
    // identify inputs by size (x: 8388608, W: 65536, b: 256)
    const float* x = nullptr;
    const float* W = nullptr;
    const float* b = nullptr;
    for (int i = 0; i < n_in; i++) {
        if (in_sizes[i] == FEAT)             b = (const float*)d_in[i];
        else if (in_sizes[i] == FEAT * FEAT) W = (const float*)d_in[i];
        else                                 x = (const float*)d_in[i];
    }

    cudaFuncSetAttribute(IterativeFixedPoint_kernel,
                         cudaFuncAttributeMaxDynamicSharedMemorySize, DYNSMEM);

    IterativeFixedPoint_kernel<<<NBLOCKS, NTHREADS, DYNSMEM>>>(
        x, W, b, (float*)d_out);
}

// round 12
// speedup vs baseline: 1.4669x; 1.4669x over previous
#include <cuda_runtime.h>
#include <cuda_fp16.h>
#include <cstdint>

// ============================================================================
// IterativeFixedPoint: z_{k+1} = tanh(W z_k + b + x), z0 = 0, 25 iterations.
// B=32768, F=256. Persistent kernel: 148 CTAs, each loops over 32-row tiles.
// ldmatrix + mma.sync.m16n8k16 f16->f32 (legal on plain sm_103 PTX target).
// W fragments register-resident (loaded once per CTA); z ping-pong in smem.
// tanh.approx for iters 1..24, exact ex2-based tanh for the final iteration.
// ============================================================================

#define FEAT       256
#define MTILE      32
#define NTILES     1024          // 32768 / 32
#define GRID       148           // persistent: one CTA per SM
#define NTHREADS   256           // 8 warps, warp tile = 32 rows x 32 cols
#define MMA_ITERS  24            // iter 1 = tanh(c); + 24 GEMM iters = 25

#define ZS_BYTES   (MTILE * 512)     // 32 rows x 256 f16 = 16 KB (x2 buffers)
#define WS_BYTES   (256 * 512)       // 256 rows x 256 f16 = 128 KB
#define DYNSMEM    (128 + 2 * ZS_BYTES + WS_BYTES)

// ---------------------------------------------------------------------------
// helpers
// ---------------------------------------------------------------------------
static __device__ __forceinline__ uint32_t smem_u32(const void* p) {
    uint32_t a;
    asm("{ .reg .u64 t; cvta.to.shared.u64 t, %1; cvt.u32.u64 %0, t; }"
        : "=r"(a) : "l"(p));
    return a;
}

// row-major K storage, 512B per row (256 f16). 16B chunks XOR-swizzled by
// (row & 7) so ldmatrix phases (8 rows, same k-chunk) are conflict-free.
static __device__ __forceinline__ uint32_t swz(uint32_t base, int row, int kchunk) {
    return base + (uint32_t)row * 512u + ((uint32_t)(kchunk ^ (row & 7)) << 4);
}

#define LDSM_X4(r0, r1, r2, r3, addr) \
    asm volatile("ldmatrix.sync.aligned.m8n8.x4.shared.b16 {%0,%1,%2,%3}, [%4];" \
                 : "=r"(r0), "=r"(r1), "=r"(r2), "=r"(r3) : "r"(addr))

// D += A*B (accumulate in place)
#define MMA16816(d, a, b) \
    asm volatile("mma.sync.aligned.m16n8k16.row.col.f32.f16.f16.f32 " \
                 "{%0,%1,%2,%3}, {%4,%5,%6,%7}, {%8,%9}, {%0,%1,%2,%3};" \
                 : "+f"((d)[0]), "+f"((d)[1]), "+f"((d)[2]), "+f"((d)[3]) \
                 : "r"((a)[0]), "r"((a)[1]), "r"((a)[2]), "r"((a)[3]), \
                   "r"((b)[0]), "r"((b)[1]))

// D = A*B + C  (separate C operand -> no accumulator-init moves)
#define MMA16816_C(d, a, b, c) \
    asm volatile("mma.sync.aligned.m16n8k16.row.col.f32.f16.f16.f32 " \
                 "{%0,%1,%2,%3}, {%4,%5,%6,%7}, {%8,%9}, {%10,%11,%12,%13};" \
                 : "=f"((d)[0]), "=f"((d)[1]), "=f"((d)[2]), "=f"((d)[3]) \
                 : "r"((a)[0]), "r"((a)[1]), "r"((a)[2]), "r"((a)[3]), \
                   "r"((b)[0]), "r"((b)[1]), \
                   "f"((c)[0]), "f"((c)[1]), "f"((c)[2]), "f"((c)[3]))

// exact-ish tanh: 1 - 2/(exp2(2u*log2e)+1); ~1e-6 rel err, exact saturation
static __device__ __forceinline__ float tanh_exact(float u) {
    float e;
    asm("ex2.approx.f32 %0, %1;" : "=f"(e) : "f"(u * 2.885390081777927f));
    float r;
    asm("rcp.approx.f32 %0, %1;" : "=f"(r) : "f"(e + 1.0f));
    return fmaf(-2.0f, r, 1.0f);
}

// hardware MUFU.TANH: 1 MUFU op, ~2^-11 relative accuracy (intermediates only)
static __device__ __forceinline__ float tanh_ap(float u) {
    float r;
    asm("tanh.approx.f32 %0, %1;" : "=f"(r) : "f"(u));
    return r;
}

static __device__ __forceinline__ uint32_t f2h2(float a, float b) {
    __half2 h = __floats2half2_rn(a, b);   // .x = a = low half = even column
    return *reinterpret_cast<uint32_t*>(&h);
}

#define STSB32(addr, v) \
    asm volatile("st.shared.b32 [%0], %1;" :: "r"(addr), "r"(v) : "memory")

// ---------------------------------------------------------------------------
// kernel
// ---------------------------------------------------------------------------
__global__ void __launch_bounds__(NTHREADS, 1)
IterativeFixedPoint_kernel(const float* __restrict__ gx,
                           const float* __restrict__ gW,
                           const float* __restrict__ gb,
                           float* __restrict__ gout)
{
    extern __shared__ char smraw[];
    const uint32_t base = (smem_u32(smraw) + 127u) & ~127u;
    const uint32_t zs0 = base;                  // z ping (32x256 f16, 16KB)
    const uint32_t zs1 = base + ZS_BYTES;       // z pong
    const uint32_t ws  = base + 2 * ZS_BYTES;   // W      (256x256 f16, 128KB)

    const int tid  = threadIdx.x;
    const int lane = tid & 31;
    const int warp = tid >> 5;
    const int C0   = warp * 32;                 // warp col slice (32 cols)
    const int rowq = lane >> 2;                 // 0..7
    const int colq = (lane & 3) * 2;            // 0,2,4,6

    const int gA   = lane >> 3;                 // ldmatrix lane group
    const int arow = ((gA & 1) * 8) + (lane & 7);
    const int akc  = (gA >> 1);
    const int brow = ((gA >> 1) * 8) + (lane & 7);
    const int bkc  = (gA & 1);

    // ---- W -> smem f16 once per CTA (thread t owns W row t)
    {
        const float4* wr = reinterpret_cast<const float4*>(gW + (size_t)tid * FEAT);
#pragma unroll
        for (int q = 0; q < 32; q++) {          // chunk q = f16 cols [8q, 8q+8)
            float4 a  = wr[2 * q];
            float4 a2 = wr[2 * q + 1];
            uint32_t v0 = f2h2(a.x,  a.y);
            uint32_t v1 = f2h2(a.z,  a.w);
            uint32_t v2 = f2h2(a2.x, a2.y);
            uint32_t v3 = f2h2(a2.z, a2.w);
            asm volatile("st.shared.v4.b32 [%0], {%1,%2,%3,%4};"
                         :: "r"(swz(ws, tid, q)), "r"(v0), "r"(v1), "r"(v2), "r"(v3)
                         : "memory");
        }
    }
    __syncthreads();

    // ---- W fragments -> registers, once (warp's 32-col slice, all K=256)
    uint32_t Wb[16][4][2];
#pragma unroll
    for (int ks = 0; ks < 16; ks++) {
#pragma unroll
        for (int np = 0; np < 2; np++) {
            LDSM_X4(Wb[ks][2 * np][0],     Wb[ks][2 * np][1],
                    Wb[ks][2 * np + 1][0], Wb[ks][2 * np + 1][1],
                    swz(ws, C0 + np * 16 + brow, ks * 2 + bkc));
        }
    }

    // ---- persistent tile loop (1024 tiles of 32 rows over 148 CTAs)
    for (int tile = blockIdx.x; tile < NTILES; tile += GRID) {
        const int gRow0 = tile * MTILE;

        // c = x + b in D-fragment layout c[mt][nb][j]
        float c[2][4][4];
        {
            float2 bp[4];
#pragma unroll
            for (int nb = 0; nb < 4; nb++)
                bp[nb] = *reinterpret_cast<const float2*>(gb + C0 + nb * 8 + colq);
#pragma unroll
            for (int mt = 0; mt < 2; mt++)
#pragma unroll
                for (int hh = 0; hh < 2; hh++) {
                    int row = mt * 16 + hh * 8 + rowq;
                    const float2* xr = reinterpret_cast<const float2*>(
                        gx + (size_t)(gRow0 + row) * FEAT);
#pragma unroll
                    for (int nb = 0; nb < 4; nb++) {
                        float2 xv = xr[(C0 + nb * 8 + colq) >> 1];
                        c[mt][nb][2 * hh + 0] = xv.x + bp[nb].x;
                        c[mt][nb][2 * hh + 1] = xv.y + bp[nb].y;
                    }
                }
        }

        // iter 1: z1 = tanh(c) -> zs0   (approx; contracts over later iters)
#pragma unroll
        for (int mt = 0; mt < 2; mt++)
#pragma unroll
            for (int hh = 0; hh < 2; hh++) {
                int row = mt * 16 + hh * 8 + rowq;
                int bc  = (C0 + colq) * 2;
#pragma unroll
                for (int nb = 0; nb < 4; nb++) {
                    uint32_t v = f2h2(tanh_ap(c[mt][nb][2 * hh]),
                                      tanh_ap(c[mt][nb][2 * hh + 1]));
                    int bcol = bc + nb * 16;
                    STSB32(swz(zs0, row, bcol >> 4) + (bcol & 15), v);
                }
            }
        __syncthreads();

        // iterations 2..25
#pragma unroll 1
        for (int it = 0; it < MMA_ITERS; it++) {
            const uint32_t rz = (it & 1) ? zs1 : zs0;
            const uint32_t wz = (it & 1) ? zs0 : zs1;

            float d[2][4][4];
#pragma unroll
            for (int ks = 0; ks < 16; ks++) {
                uint32_t a[2][4];
#pragma unroll
                for (int mt = 0; mt < 2; mt++)
                    LDSM_X4(a[mt][0], a[mt][1], a[mt][2], a[mt][3],
                            swz(rz, mt * 16 + arow, ks * 2 + akc));
                if (ks == 0) {
#pragma unroll
                    for (int mt = 0; mt < 2; mt++)
#pragma unroll
                        for (int nb = 0; nb < 4; nb++)
                            MMA16816_C(d[mt][nb], a[mt], Wb[0][nb], c[mt][nb]);
                } else {
#pragma unroll
                    for (int mt = 0; mt < 2; mt++)
#pragma unroll
                        for (int nb = 0; nb < 4; nb++)
                            MMA16816(d[mt][nb], a[mt], Wb[ks][nb]);
                }
            }

            if (it < MMA_ITERS - 1) {
                // intermediate epilogue: approx tanh -> z smem (pong)
#pragma unroll
                for (int mt = 0; mt < 2; mt++)
#pragma unroll
                    for (int hh = 0; hh < 2; hh++) {
                        int row = mt * 16 + hh * 8 + rowq;
                        int bc  = (C0 + colq) * 2;
#pragma unroll
                        for (int nb = 0; nb < 4; nb++) {
                            uint32_t v = f2h2(tanh_ap(d[mt][nb][2 * hh]),
                                              tanh_ap(d[mt][nb][2 * hh + 1]));
                            int bcol = bc + nb * 16;
                            STSB32(swz(wz, row, bcol >> 4) + (bcol & 15), v);
                        }
                    }
                __syncthreads();
            } else {
                // final epilogue: exact tanh -> gmem f32
#pragma unroll
                for (int mt = 0; mt < 2; mt++)
#pragma unroll
                    for (int hh = 0; hh < 2; hh++) {
                        int row = gRow0 + mt * 16 + hh * 8 + rowq;
                        float2* o = reinterpret_cast<float2*>(
                            gout + (size_t)row * FEAT);
#pragma unroll
                        for (int nb = 0; nb < 4; nb++) {
                            float2 v = make_float2(tanh_exact(d[mt][nb][2 * hh]),
                                                   tanh_exact(d[mt][nb][2 * hh + 1]));
                            o[(C0 + nb * 8 + colq) >> 1] = v;
                        }
                    }
                // no barrier: next tile's iter-1 writes zs0; stragglers here
                // only read zs1 (it=23) and gmem -> no conflict.
            }
        }
    }
}

// ---------------------------------------------------------------------------
// launch
// ---------------------------------------------------------------------------
extern "C" void kernel_launch(void* const* d_in, const int* in_sizes, int n_in,
                              void* d_out, int out_size)
{
    // identify inputs by size (x: 8388608, W: 65536, b: 256)
    const float* x = nullptr;
    const float* W = nullptr;
    const float* b = nullptr;
    for (int i = 0; i < n_in; i++) {
        if (in_sizes[i] == FEAT)             b = (const float*)d_in[i];
        else if (in_sizes[i] == FEAT * FEAT) W = (const float*)d_in[i];
        else                                 x = (const float*)d_in[i];
    }

    cudaFuncSetAttribute(IterativeFixedPoint_kernel,
                         cudaFuncAttributeMaxDynamicSharedMemorySize, DYNSMEM);

    IterativeFixedPoint_kernel<<<GRID, NTHREADS, DYNSMEM>>>(
        x, W, b, (float*)d_out);
}

// round 14
// speedup vs baseline: 1.6601x; 1.1317x over previous
#include <cuda_runtime.h>
#include <cuda_fp16.h>
#include <cstdint>

// ============================================================================
// IterativeFixedPoint: z_{k+1} = tanh(W z_k + b + x), z0 = 0, 25 iterations.
// B=32768, F=256. Persistent kernel (148 CTAs), 32-row tiles split into TWO
// independent 16-row sub-tiles, phase-offset by half an iteration so each
// warp's MMA issue gaps (tensor pipe busy) absorb the other sub-tile's
// tanh/pack/STS epilogue. ldmatrix + mma.sync.m16n8k16 f16->f32; W fragments
// register-resident. tanh.approx.f16x2 for intermediates, exact f32 final.
// (Resubmission of R13: container infra failure, kernel never ran.)
// ============================================================================

#define FEAT       256
#define MSUB       16            // rows per sub-tile
#define NTILES     1024          // 32768 / 32
#define GRID       148
#define NTHREADS   256           // 8 warps, each owns a 32-col slice
#define LOOP_ITERS 22            // k=2 and k=25 peeled; total MMA iters = 24

#define ZS_BYTES   (MSUB * 512)  // 16 rows x 256 f16 = 8 KB per sub-tile
#define WS_BYTES   (256 * 512)   // 128 KB
#define DYNSMEM    (128 + 2 * ZS_BYTES + WS_BYTES)

// ---------------------------------------------------------------------------
// helpers
// ---------------------------------------------------------------------------
static __device__ __forceinline__ uint32_t smem_u32(const void* p) {
    uint32_t a;
    asm("{ .reg .u64 t; cvta.to.shared.u64 t, %1; cvt.u32.u64 %0, t; }"
        : "=r"(a) : "l"(p));
    return a;
}

// row-major K storage, 512B/row (256 f16); 16B chunks XOR-swizzled by (row&7)
static __device__ __forceinline__ uint32_t swz(uint32_t base, int row, int kchunk) {
    return base + (uint32_t)row * 512u + ((uint32_t)(kchunk ^ (row & 7)) << 4);
}

#define LDSM_X4(r0, r1, r2, r3, addr) \
    asm volatile("ldmatrix.sync.aligned.m8n8.x4.shared.b16 {%0,%1,%2,%3}, [%4];" \
                 : "=r"(r0), "=r"(r1), "=r"(r2), "=r"(r3) : "r"(addr))

#define MMA16816(d, a, b) \
    asm volatile("mma.sync.aligned.m16n8k16.row.col.f32.f16.f16.f32 " \
                 "{%0,%1,%2,%3}, {%4,%5,%6,%7}, {%8,%9}, {%0,%1,%2,%3};" \
                 : "+f"((d)[0]), "+f"((d)[1]), "+f"((d)[2]), "+f"((d)[3]) \
                 : "r"((a)[0]), "r"((a)[1]), "r"((a)[2]), "r"((a)[3]), \
                   "r"((b)[0]), "r"((b)[1]))

#define MMA16816_C(d, a, b, c) \
    asm volatile("mma.sync.aligned.m16n8k16.row.col.f32.f16.f16.f32 " \
                 "{%0,%1,%2,%3}, {%4,%5,%6,%7}, {%8,%9}, {%10,%11,%12,%13};" \
                 : "=f"((d)[0]), "=f"((d)[1]), "=f"((d)[2]), "=f"((d)[3]) \
                 : "r"((a)[0]), "r"((a)[1]), "r"((a)[2]), "r"((a)[3]), \
                   "r"((b)[0]), "r"((b)[1]), \
                   "f"((c)[0]), "f"((c)[1]), "f"((c)[2]), "f"((c)[3]))

// exact tanh: 1 - 2/(exp2(2u*log2e)+1); ~1e-6 rel err, exact saturation
static __device__ __forceinline__ float tanh_exact(float u) {
    float e;
    asm("ex2.approx.f32 %0, %1;" : "=f"(e) : "f"(u * 2.885390081777927f));
    float r;
    asm("rcp.approx.f32 %0, %1;" : "=f"(r) : "f"(e + 1.0f));
    return fmaf(-2.0f, r, 1.0f);
}

static __device__ __forceinline__ uint32_t tanh_h2(uint32_t u) {
    uint32_t r;
    asm("tanh.approx.f16x2 %0, %1;" : "=r"(r) : "r"(u));
    return r;
}

static __device__ __forceinline__ uint32_t f2h2(float a, float b) {
    __half2 h = __floats2half2_rn(a, b);   // .x = a = low half = even column
    return *reinterpret_cast<uint32_t*>(&h);
}

#define STSB32(addr, v) \
    asm volatile("st.shared.b32 [%0], %1;" :: "r"(addr), "r"(v) : "memory")

// one epilogue unit e in [0,8): z[dst] = tanh~(src) for (hh, nb) = (e>>2, e&3)
static __device__ __forceinline__ void epi_unit(
    int e, const float (&src)[4][4], uint32_t dst,
    int rowq, int colq, int C0)
{
    const int hh  = e >> 2, nb = e & 3;
    const int row = hh * 8 + rowq;
    const int bcol = (C0 + colq) * 2 + nb * 16;
    uint32_t v = tanh_h2(f2h2(src[nb][2 * hh], src[nb][2 * hh + 1]));
    STSB32(swz(dst, row, bcol >> 4) + (bcol & 15), v);
}

// full 8-unit epilogue (prologue use, no MMA to hide under)
static __device__ __forceinline__ void epi8(
    const float (&src)[4][4], uint32_t dst, int rowq, int colq, int C0)
{
#pragma unroll
    for (int e = 0; e < 8; e++) epi_unit(e, src, dst, rowq, colq, C0);
}

// half-iteration: d = W * z(zbuf) + c for one 16-row sub-tile; while the
// tensor pipe grinds, interleave the OTHER sub-tile's epilogue (src -> dstbuf)
template <int EPI>
static __device__ __forceinline__ void half_step(
    float (&d)[4][4], uint32_t zbuf, const float (&c)[4][4],
    const float (&src)[4][4], uint32_t dstbuf,
    const uint32_t (&Wb)[16][4][2],
    int arow, int akc, int rowq, int colq, int C0)
{
#pragma unroll
    for (int ks = 0; ks < 16; ks++) {
        uint32_t a[4];
        LDSM_X4(a[0], a[1], a[2], a[3], swz(zbuf, arow, ks * 2 + akc));
        if (ks == 0) {
#pragma unroll
            for (int nb = 0; nb < 4; nb++)
                MMA16816_C(d[nb], a, Wb[0][nb], c[nb]);
        } else {
#pragma unroll
            for (int nb = 0; nb < 4; nb++)
                MMA16816(d[nb], a, Wb[ks][nb]);
        }
        if (EPI && ks >= 4 && ks < 12)
            epi_unit(ks - 4, src, dstbuf, rowq, colq, C0);
    }
}

// c = x + b in fragment layout for one 16-row sub-tile
static __device__ __forceinline__ void load_c(
    float (&c)[4][4], const float* gx, const float2 (&bp)[4],
    int gRowBase, int rowq, int colq, int C0)
{
#pragma unroll
    for (int hh = 0; hh < 2; hh++) {
        const float2* xr = reinterpret_cast<const float2*>(
            gx + (size_t)(gRowBase + hh * 8 + rowq) * FEAT);
#pragma unroll
        for (int nb = 0; nb < 4; nb++) {
            float2 xv = xr[(C0 + nb * 8 + colq) >> 1];
            c[nb][2 * hh + 0] = xv.x + bp[nb].x;
            c[nb][2 * hh + 1] = xv.y + bp[nb].y;
        }
    }
}

// final exact epilogue: gout = tanh(d), f32
static __device__ __forceinline__ void final_store(
    const float (&d)[4][4], float* gout, int gRowBase,
    int rowq, int colq, int C0)
{
#pragma unroll
    for (int hh = 0; hh < 2; hh++) {
        int row = gRowBase + hh * 8 + rowq;
        float2* o = reinterpret_cast<float2*>(gout + (size_t)row * FEAT);
#pragma unroll
        for (int nb = 0; nb < 4; nb++)
            o[(C0 + nb * 8 + colq) >> 1] =
                make_float2(tanh_exact(d[nb][2 * hh]),
                            tanh_exact(d[nb][2 * hh + 1]));
    }
}

// ---------------------------------------------------------------------------
// kernel
// ---------------------------------------------------------------------------
__global__ void __launch_bounds__(NTHREADS, 1)
IterativeFixedPoint_kernel(const float* __restrict__ gx,
                           const float* __restrict__ gW,
                           const float* __restrict__ gb,
                           float* __restrict__ gout)
{
    extern __shared__ char smraw[];
    const uint32_t base = (smem_u32(smraw) + 127u) & ~127u;
    const uint32_t zsA = base;                  // sub-tile A z (16x256 f16)
    const uint32_t zsB = base + ZS_BYTES;       // sub-tile B z
    const uint32_t ws  = base + 2 * ZS_BYTES;   // W (256x256 f16, 128KB)

    const int tid  = threadIdx.x;
    const int lane = tid & 31;
    const int warp = tid >> 5;
    const int C0   = warp * 32;                 // warp col slice
    const int rowq = lane >> 2;
    const int colq = (lane & 3) * 2;

    const int gA   = lane >> 3;
    const int arow = ((gA & 1) * 8) + (lane & 7);
    const int akc  = (gA >> 1);
    const int brow = ((gA >> 1) * 8) + (lane & 7);
    const int bkc  = (gA & 1);

    // ---- W -> smem f16 once (thread t owns W row t)
    {
        const float4* wr = reinterpret_cast<const float4*>(gW + (size_t)tid * FEAT);
#pragma unroll
        for (int q = 0; q < 32; q++) {
            float4 a  = wr[2 * q];
            float4 a2 = wr[2 * q + 1];
            uint32_t v0 = f2h2(a.x,  a.y);
            uint32_t v1 = f2h2(a.z,  a.w);
            uint32_t v2 = f2h2(a2.x, a2.y);
            uint32_t v3 = f2h2(a2.z, a2.w);
            asm volatile("st.shared.v4.b32 [%0], {%1,%2,%3,%4};"
                         :: "r"(swz(ws, tid, q)), "r"(v0), "r"(v1), "r"(v2), "r"(v3)
                         : "memory");
        }
    }
    __syncthreads();

    // ---- W fragments -> registers, once per CTA
    uint32_t Wb[16][4][2];
#pragma unroll
    for (int ks = 0; ks < 16; ks++)
#pragma unroll
        for (int np = 0; np < 2; np++)
            LDSM_X4(Wb[ks][2 * np][0],     Wb[ks][2 * np][1],
                    Wb[ks][2 * np + 1][0], Wb[ks][2 * np + 1][1],
                    swz(ws, C0 + np * 16 + brow, ks * 2 + bkc));

    // ---- b fragment (constant across tiles)
    float2 bp[4];
#pragma unroll
    for (int nb = 0; nb < 4; nb++)
        bp[nb] = *reinterpret_cast<const float2*>(gb + C0 + nb * 8 + colq);

    // ---- persistent tile loop (1024 tiles of 32 rows = 2 sub-tiles)
    for (int tile = blockIdx.x; tile < NTILES; tile += GRID) {
        const int gRow0 = tile * 32;

        float cA[4][4], cB[4][4];
        load_c(cA, gx, bp, gRow0,      rowq, colq, C0);
        load_c(cB, gx, bp, gRow0 + 16, rowq, colq, C0);

        // iter 1 (A): zA1 = tanh~(cA)
        epi8(cA, zsA, rowq, colq, C0);
        __syncthreads();

        float dA[4][4], dB[4][4];

        // k = 2: A's MMA hides B's iter-1 epilogue (zB1 = tanh~(cB))
        half_step<1>(dA, zsA, cA, cB, zsB, Wb, arow, akc, rowq, colq, C0);
        __syncthreads();
        half_step<1>(dB, zsB, cB, dA, zsA, Wb, arow, akc, rowq, colq, C0);
        __syncthreads();

        // k = 3..24
#pragma unroll 1
        for (int k = 0; k < LOOP_ITERS; k++) {
            half_step<1>(dA, zsA, cA, dB, zsB, Wb, arow, akc, rowq, colq, C0);
            __syncthreads();
            half_step<1>(dB, zsB, cB, dA, zsA, Wb, arow, akc, rowq, colq, C0);
            __syncthreads();
        }

        // k = 25: last B half has no smem epilogue; finals are exact f32
        half_step<1>(dA, zsA, cA, dB, zsB, Wb, arow, akc, rowq, colq, C0);
        __syncthreads();
        half_step<0>(dB, zsB, cB, dB, zsB, Wb, arow, akc, rowq, colq, C0);

        final_store(dA, gout, gRow0,      rowq, colq, C0);
        final_store(dB, gout, gRow0 + 16, rowq, colq, C0);
        __syncthreads();   // z buffers reused by next tile's prologue
    }
}

// ---------------------------------------------------------------------------
// launch
// ---------------------------------------------------------------------------
extern "C" void kernel_launch(void* const* d_in, const int* in_sizes, int n_in,
                              void* d_out, int out_size)
{
    // identify inputs by size (x: 8388608, W: 65536, b: 256)
    const float* x = nullptr;
    const float* W = nullptr;
    const float* b = nullptr;
    for (int i = 0; i < n_in; i++) {
        if (in_sizes[i] == FEAT)             b = (const float*)d_in[i];
        else if (in_sizes[i] == FEAT * FEAT) W = (const float*)d_in[i];
        else                                 x = (const float*)d_in[i];
    }

    cudaFuncSetAttribute(IterativeFixedPoint_kernel,
                         cudaFuncAttributeMaxDynamicSharedMemorySize, DYNSMEM);

    IterativeFixedPoint_kernel<<<GRID, NTHREADS, DYNSMEM>>>(
        x, W, b, (float*)d_out);
}